// round 2
// baseline (speedup 1.0000x reference)
#include <cuda_runtime.h>
#include <float.h>
#include <math.h>

#define B_ 8
#define C_ 32
#define H_ 512
#define W_ 512
#define HW_ (H_*W_)

typedef unsigned long long u64;

// Scratch (allocation-free rule: static __device__ arrays)
__device__ float g_fs[B_*C_*H_*W_];   // conv1x1 output (pre-attention)
__device__ float g_cm[B_*H_*W_];      // channel max plane
__device__ float g_ca[B_*H_*W_];      // channel mean plane

__device__ __forceinline__ float fsigmoid(float z) {
    return 1.0f / (1.0f + __expf(-z));
}

// ---- packed f32x2 helpers (sm_10x) ----
__device__ __forceinline__ u64 pack2(float lo, float hi) {
    u64 r; asm("mov.b64 %0, {%1,%2};" : "=l"(r) : "f"(lo), "f"(hi)); return r;
}
__device__ __forceinline__ u64 dup2(float v) { return pack2(v, v); }
__device__ __forceinline__ void unpack2(u64 v, float &lo, float &hi) {
    asm("mov.b64 {%0,%1}, %2;" : "=f"(lo), "=f"(hi) : "l"(v));
}
__device__ __forceinline__ u64 fma2(u64 a, u64 b, u64 c) {
    u64 d; asm("fma.rn.f32x2 %0, %1, %2, %3;" : "=l"(d) : "l"(a), "l"(b), "l"(c)); return d;
}
__device__ __forceinline__ u64 add2(u64 a, u64 b) {
    u64 d; asm("add.rn.f32x2 %0, %1, %2;" : "=l"(d) : "l"(a), "l"(b)); return d;
}

// ---------------------------------------------------------------------------
// Kernel A: per 2x2 patch — patch max/avg -> gate -> fused (concat + 1x1 conv)
// out[o] = sum_c x[c]*(gate[c]*w1[o,c] + w2[o,c]) + b[o]
// 2 threads per patch (16 output channels each) as f32x2 output pairs.
// Block = 256 threads = 128 patches x 2 halves. Grid = (2, 256, 8).
// ---------------------------------------------------------------------------
__global__ __launch_bounds__(256, 1)
void kernelA(const float* __restrict__ x,
             const float* __restrict__ mlp_w,
             const float* __restrict__ mlp_b,
             const float* __restrict__ conv_w,
             const float* __restrict__ conv_b)
{
    __shared__ __align__(16) float2 s_w1[32][16];  // [c][opair]
    __shared__ __align__(16) float2 s_w2[32][16];
    __shared__ __align__(8)  float  s_b[32];
    __shared__ float2 s_red[128][4];               // half1 partial (mx, sum) per px

    const int tid = threadIdx.x;
    for (int i = tid; i < 512; i += 256) {
        int op = i & 15, c = i >> 4;
        s_w1[c][op] = make_float2(conv_w[(2*op)*64 + c],      conv_w[(2*op+1)*64 + c]);
        s_w2[c][op] = make_float2(conv_w[(2*op)*64 + 32 + c], conv_w[(2*op+1)*64 + 32 + c]);
    }
    if (tid < 32) s_b[tid] = conv_b[tid];
    __syncthreads();

    const int half = tid >> 7;         // 0: outputs 0-15, 1: outputs 16-31
    const int pi   = tid & 127;
    const int wp   = blockIdx.x * 128 + pi;
    const int hp   = blockIdx.y;
    const int b    = blockIdx.z;

    const float2* __restrict__ x2 = (const float2*)x;
    const float mw  = __ldg(mlp_w);
    const float mb2 = 2.0f * __ldg(mlp_b);

    u64 acc[8][4];
#pragma unroll
    for (int k = 0; k < 8; k++)
#pragma unroll
        for (int j = 0; j < 4; j++) acc[k][j] = 0ull;

#pragma unroll 2
    for (int c = 0; c < 32; c++) {
        unsigned p = (((unsigned)(b * 32 + c)) * 512u + 2u * hp) * 256u + wp;
        float2 r0 = x2[p];
        float2 r1 = x2[p + 256];
        float m = fmaxf(fmaxf(r0.x, r0.y), fmaxf(r1.x, r1.y));
        float a = 0.25f * ((r0.x + r0.y) + (r1.x + r1.y));
        float g = fsigmoid(fmaf(m + a, mw, mb2));
        u64 gg = dup2(g);
        u64 v0 = dup2(r0.x), v1 = dup2(r0.y), v2 = dup2(r1.x), v3 = dup2(r1.y);
        const u64* __restrict__ w1p = (const u64*)&s_w1[c][half * 8];
        const u64* __restrict__ w2p = (const u64*)&s_w2[c][half * 8];
#pragma unroll
        for (int k = 0; k < 8; k++) {
            u64 we = fma2(gg, w1p[k], w2p[k]);     // gate*w1 + w2, per output pair
            acc[k][0] = fma2(v0, we, acc[k][0]);
            acc[k][1] = fma2(v1, we, acc[k][1]);
            acc[k][2] = fma2(v2, we, acc[k][2]);
            acc[k][3] = fma2(v3, we, acc[k][3]);
        }
    }

    // bias add (pairs)
    const u64* __restrict__ bp = (const u64*)&s_b[half * 16];
#pragma unroll
    for (int k = 0; k < 8; k++) {
        u64 bk = bp[k];
#pragma unroll
        for (int j = 0; j < 4; j++) acc[k][j] = add2(acc[k][j], bk);
    }

    // per-pixel partial channel max / sum over this half's 16 outputs
    float mx[4], sm[4];
#pragma unroll
    for (int j = 0; j < 4; j++) { mx[j] = -FLT_MAX; sm[j] = 0.f; }
#pragma unroll
    for (int k = 0; k < 8; k++) {
#pragma unroll
        for (int j = 0; j < 4; j++) {
            float lo, hi; unpack2(acc[k][j], lo, hi);
            mx[j] = fmaxf(mx[j], fmaxf(lo, hi));
            sm[j] += lo + hi;
        }
    }
    if (half == 1) {
#pragma unroll
        for (int j = 0; j < 4; j++) s_red[pi][j] = make_float2(mx[j], sm[j]);
    }

    // fs stores: pair (px0,px1) along w per output channel -> STG.64 coalesced
    float2* __restrict__ fs2 = (float2*)g_fs;
#pragma unroll
    for (int k = 0; k < 8; k++) {
        float x0, y0, x1, y1, x2_, y2_, x3, y3;
        unpack2(acc[k][0], x0, y0);
        unpack2(acc[k][1], x1, y1);
        unpack2(acc[k][2], x2_, y2_);
        unpack2(acc[k][3], x3, y3);
        int o0 = half * 16 + 2 * k;
        unsigned p0 = (((unsigned)(b * 32 + o0)) * 512u + 2u * hp) * 256u + wp;
        unsigned p1 = p0 + (unsigned)HW_ / 2u;  // o0+1 plane
        fs2[p0]       = make_float2(x0, x1);
        fs2[p0 + 256] = make_float2(x2_, x3);
        fs2[p1]       = make_float2(y0, y1);
        fs2[p1 + 256] = make_float2(y2_, y3);
    }

    __syncthreads();
    if (half == 0) {
#pragma unroll
        for (int j = 0; j < 4; j++) {
            float2 r = s_red[pi][j];
            mx[j] = fmaxf(mx[j], r.x);
            sm[j] = (sm[j] + r.y) * (1.0f / 32.0f);
        }
        unsigned q = (((unsigned)b) * 512u + 2u * hp) * 256u + wp;
        ((float2*)g_cm)[q]       = make_float2(mx[0], mx[1]);
        ((float2*)g_cm)[q + 256] = make_float2(mx[2], mx[3]);
        ((float2*)g_ca)[q]       = make_float2(sm[0], sm[1]);
        ((float2*)g_ca)[q + 256] = make_float2(sm[2], sm[3]);
    }
}

// ---------------------------------------------------------------------------
// Kernel B: 7x7 SAME conv on [cm;ca] (2->32 ch), sigmoid, multiply by fs.
// f32x2 accumulators over output-channel pairs; weights as ulonglong2 from smem.
// ---------------------------------------------------------------------------
#define TW 64
#define TH 16

__global__ __launch_bounds__(256, 1)
void kernelB(const float* __restrict__ cow,
             const float* __restrict__ cob,
             float* __restrict__ out)
{
    __shared__ __align__(16) float s_in[2][TH + 6][TW + 6];
    __shared__ __align__(16) float s_w[98][32];   // [tap][o], tap = j*49+dy*7+dx
    __shared__ __align__(8)  float s_b[32];

    const int tid = threadIdx.x;
    const int b   = blockIdx.z;
    const int tyb = blockIdx.y * TH;
    const int txb = blockIdx.x * TW;

    for (int i = tid; i < 98 * 32; i += 256) {
        int o = i & 31, tap = i >> 5;
        s_w[tap][o] = cow[o * 98 + tap];
    }
    if (tid < 32) s_b[tid] = cob[tid];

    for (int i = tid; i < 2 * (TH + 6) * (TW + 6); i += 256) {
        int plane = i / ((TH + 6) * (TW + 6));
        int rem   = i % ((TH + 6) * (TW + 6));
        int r  = rem / (TW + 6);
        int cc = rem % (TW + 6);
        int h = tyb - 3 + r;
        int w = txb - 3 + cc;
        float v = 0.f;
        if (h >= 0 && h < H_ && w >= 0 && w < W_) {
            const float* src = plane ? g_ca : g_cm;
            v = src[((unsigned)b * H_ + h) * W_ + w];
        }
        s_in[plane][r][cc] = v;
    }
    __syncthreads();

    const int tx  = tid & 63;   // pixel column within tile
    const int ty0 = tid >> 6;   // 0..3 -> rows ty0*4 .. ty0*4+3

    const u64* __restrict__ bpair = (const u64*)s_b;

#pragma unroll 1
    for (int py = 0; py < 4; py++) {
        const int ty = ty0 * 4 + py;
        u64 acc[16];
#pragma unroll
        for (int k = 0; k < 16; k++) acc[k] = bpair[k];

#pragma unroll 1
        for (int j = 0; j < 2; j++) {
#pragma unroll 1
            for (int dy = 0; dy < 7; dy++) {
                const float* __restrict__ row = &s_in[j][ty + dy][tx];
                const int tapbase = j * 49 + dy * 7;
#pragma unroll
                for (int dx = 0; dx < 7; dx++) {
                    u64 vv = dup2(row[dx]);
                    const ulonglong2* __restrict__ w2 = (const ulonglong2*)&s_w[tapbase + dx][0];
#pragma unroll
                    for (int k4 = 0; k4 < 8; k4++) {
                        ulonglong2 wp = w2[k4];
                        acc[2*k4]   = fma2(vv, wp.x, acc[2*k4]);
                        acc[2*k4+1] = fma2(vv, wp.y, acc[2*k4+1]);
                    }
                }
            }
        }

        const int h = tyb + ty;
        const int w = txb + tx;
        unsigned fbase = (((unsigned)b * 32) * 512u + h) * 512u + w;
#pragma unroll
        for (int k = 0; k < 16; k++) {
            float a0, a1; unpack2(acc[k], a0, a1);
            unsigned i0 = fbase + (unsigned)(2*k) * (unsigned)HW_;
            unsigned i1 = i0 + (unsigned)HW_;
            out[i0] = fsigmoid(a0) * g_fs[i0];
            out[i1] = fsigmoid(a1) * g_fs[i1];
        }
    }
}

extern "C" void kernel_launch(void* const* d_in, const int* in_sizes, int n_in,
                              void* d_out, int out_size)
{
    (void)in_sizes; (void)n_in; (void)out_size;
    const float* x      = (const float*)d_in[0];
    const float* mlp_w  = (const float*)d_in[1];
    const float* mlp_b  = (const float*)d_in[2];
    const float* conv_w = (const float*)d_in[3];
    const float* conv_b = (const float*)d_in[4];
    const float* cow    = (const float*)d_in[5];
    const float* cob    = (const float*)d_in[6];
    float* out = (float*)d_out;

    kernelA<<<dim3(2, 256, 8), 256>>>(x, mlp_w, mlp_b, conv_w, conv_b);
    kernelB<<<dim3(W_ / TW, H_ / TH, 8), 256>>>(cow, cob, out);
}

// round 3
// speedup vs baseline: 2.3246x; 2.3246x over previous
#include <cuda_runtime.h>
#include <float.h>
#include <math.h>

#define B_ 8
#define C_ 32
#define H_ 512
#define W_ 512
#define HW_ (H_*W_)

typedef unsigned long long u64;

// Scratch (allocation-free rule: static __device__ arrays)
__device__ float g_fs[B_*C_*H_*W_];   // conv1x1 output (pre-attention)
__device__ float g_cm[B_*H_*W_];      // channel max plane
__device__ float g_ca[B_*H_*W_];      // channel mean plane

__device__ __forceinline__ float fsigmoid(float z) {
    return 1.0f / (1.0f + __expf(-z));
}

// ---- packed f32x2 helpers (sm_10x) ----
__device__ __forceinline__ u64 pack2(float lo, float hi) {
    u64 r; asm("mov.b64 %0, {%1,%2};" : "=l"(r) : "f"(lo), "f"(hi)); return r;
}
__device__ __forceinline__ u64 dup2(float v) { return pack2(v, v); }
__device__ __forceinline__ void unpack2(u64 v, float &lo, float &hi) {
    asm("mov.b64 {%0,%1}, %2;" : "=f"(lo), "=f"(hi) : "l"(v));
}
__device__ __forceinline__ u64 fma2(u64 a, u64 b, u64 c) {
    u64 d; asm("fma.rn.f32x2 %0, %1, %2, %3;" : "=l"(d) : "l"(a), "l"(b), "l"(c)); return d;
}
__device__ __forceinline__ u64 add2(u64 a, u64 b) {
    u64 d; asm("add.rn.f32x2 %0, %1, %2;" : "=l"(d) : "l"(a), "l"(b)); return d;
}

// ---------------------------------------------------------------------------
// Kernel A: per 2x2 patch — patch max/avg -> gate -> fused (concat + 1x1 conv)
// out[o] = sum_c x[c]*(gate[c]*w1[o,c] + w2[o,c]) + b[o]
// 2 threads per patch; each owns 16 output channels.
// Accumulators are f32x2 over the horizontal pixel pair of the patch.
// Block = 256 threads = 128 patches x 2 halves. Grid = (2, 256, 8).
// ---------------------------------------------------------------------------
__global__ __launch_bounds__(256, 2)
void kernelA(const float* __restrict__ x,
             const float* __restrict__ mlp_w,
             const float* __restrict__ mlp_b,
             const float* __restrict__ conv_w,
             const float* __restrict__ conv_b)
{
    __shared__ __align__(16) u64 s_w1d[32][32];   // [c][o] = dup(conv_w[o, c])
    __shared__ __align__(16) u64 s_w2d[32][32];   // [c][o] = dup(conv_w[o, 32+c])
    __shared__ __align__(16) u64 s_bd[32];
    __shared__ float2 s_red[128][4];              // half-1 partial (mx, sum) per px

    const int tid = threadIdx.x;
    for (int i = tid; i < 1024; i += 256) {
        int o = i & 31, c = i >> 5;
        s_w1d[c][o] = dup2(conv_w[o * 64 + c]);
        s_w2d[c][o] = dup2(conv_w[o * 64 + 32 + c]);
    }
    if (tid < 32) s_bd[tid] = dup2(conv_b[tid]);
    __syncthreads();

    const int half = tid >> 7;         // 0: outputs 0-15, 1: outputs 16-31
    const int pi   = tid & 127;
    const int wp   = blockIdx.x * 128 + pi;   // patch col (float2 units)
    const int hp   = blockIdx.y;              // patch row
    const int b    = blockIdx.z;

    const u64* __restrict__ x2 = (const u64*)x;
    const float mw  = __ldg(mlp_w);
    const float mb2 = 2.0f * __ldg(mlp_b);

    u64 acc[16][2];   // [local channel][pair: 0=top row, 1=bottom row]
#pragma unroll
    for (int k = 0; k < 16; k++) { acc[k][0] = 0ull; acc[k][1] = 0ull; }

#pragma unroll 2
    for (int c = 0; c < 32; c++) {
        unsigned p = (((unsigned)(b * 32 + c)) * 512u + 2u * hp) * 256u + wp;
        u64 r0 = x2[p];          // two adjacent pixels, top row
        u64 r1 = x2[p + 256];    // two adjacent pixels, bottom row
        float r0x, r0y, r1x, r1y;
        unpack2(r0, r0x, r0y);
        unpack2(r1, r1x, r1y);
        float m = fmaxf(fmaxf(r0x, r0y), fmaxf(r1x, r1y));
        float a = 0.25f * ((r0x + r0y) + (r1x + r1y));
        float g = fsigmoid(fmaf(m + a, mw, mb2));
        u64 gg = dup2(g);
        const ulonglong2* __restrict__ w1p = (const ulonglong2*)&s_w1d[c][half * 16];
        const ulonglong2* __restrict__ w2p = (const ulonglong2*)&s_w2d[c][half * 16];
#pragma unroll
        for (int k2 = 0; k2 < 8; k2++) {
            ulonglong2 a1 = w1p[k2];
            ulonglong2 a2 = w2p[k2];
            u64 we0 = fma2(gg, a1.x, a2.x);     // dup'd effective weight
            u64 we1 = fma2(gg, a1.y, a2.y);
            acc[2*k2  ][0] = fma2(r0, we0, acc[2*k2  ][0]);
            acc[2*k2  ][1] = fma2(r1, we0, acc[2*k2  ][1]);
            acc[2*k2+1][0] = fma2(r0, we1, acc[2*k2+1][0]);
            acc[2*k2+1][1] = fma2(r1, we1, acc[2*k2+1][1]);
        }
    }

    // bias add
#pragma unroll
    for (int k = 0; k < 16; k++) {
        u64 bk = s_bd[half * 16 + k];
        acc[k][0] = add2(acc[k][0], bk);
        acc[k][1] = add2(acc[k][1], bk);
    }

    // per-pixel partial channel max/sum over this half's 16 channels
    // px order: 0=top-left 1=top-right 2=bot-left 3=bot-right
    float mx[4], sm[4];
#pragma unroll
    for (int j = 0; j < 4; j++) { mx[j] = -FLT_MAX; sm[j] = 0.f; }
#pragma unroll
    for (int k = 0; k < 16; k++) {
        float lo, hi;
        unpack2(acc[k][0], lo, hi);
        mx[0] = fmaxf(mx[0], lo); sm[0] += lo;
        mx[1] = fmaxf(mx[1], hi); sm[1] += hi;
        unpack2(acc[k][1], lo, hi);
        mx[2] = fmaxf(mx[2], lo); sm[2] += lo;
        mx[3] = fmaxf(mx[3], hi); sm[3] += hi;
    }
    if (half == 1) {
#pragma unroll
        for (int j = 0; j < 4; j++) s_red[pi][j] = make_float2(mx[j], sm[j]);
    }

    // fs stores: u64 = adjacent pixel pair, coalesced within warp
    u64* __restrict__ fs2 = (u64*)g_fs;
#pragma unroll
    for (int k = 0; k < 16; k++) {
        int o = half * 16 + k;
        unsigned p = (((unsigned)(b * 32 + o)) * 512u + 2u * hp) * 256u + wp;
        fs2[p]       = acc[k][0];
        fs2[p + 256] = acc[k][1];
    }

    __syncthreads();
    if (half == 0) {
#pragma unroll
        for (int j = 0; j < 4; j++) {
            float2 r = s_red[pi][j];
            mx[j] = fmaxf(mx[j], r.x);
            sm[j] = (sm[j] + r.y) * (1.0f / 32.0f);
        }
        unsigned q = (((unsigned)b) * 512u + 2u * hp) * 256u + wp;
        ((float2*)g_cm)[q]       = make_float2(mx[0], mx[1]);
        ((float2*)g_cm)[q + 256] = make_float2(mx[2], mx[3]);
        ((float2*)g_ca)[q]       = make_float2(sm[0], sm[1]);
        ((float2*)g_ca)[q + 256] = make_float2(sm[2], sm[3]);
    }
}

// ---------------------------------------------------------------------------
// Kernel B: 7x7 SAME conv on [cm;ca] (2->32 ch), sigmoid, multiply by fs.
// Thread = 8 consecutive pixels (4 f32x2 pairs) x 4 output channels.
// Weights pre-duplicated in smem as u64; input row window cached in registers.
// Block 256 = 8 channel-groups x 32 octets; tile 64w x 4h. Grid (8,128,8).
// ---------------------------------------------------------------------------
#define THB 4

__global__ __launch_bounds__(256, 2)
void kernelB(const float* __restrict__ cow,
             const float* __restrict__ cob,
             float* __restrict__ out)
{
    __shared__ __align__(16) float s_in[2][THB + 6][72];
    __shared__ __align__(16) u64 s_wd[98][32];   // [tap][o] dup'd
    __shared__ __align__(16) u64 s_bd[32];

    const int tid = threadIdx.x;
    const int b   = blockIdx.z;
    const int tyb = blockIdx.y * THB;
    const int txb = blockIdx.x * 64;

    // weights: coalesced gmem read, dup into smem
    for (int i = tid; i < 98 * 32; i += 256) {
        int o = i / 98, tap = i - o * 98;
        float w = cow[i];
        s_wd[tap][o] = pack2(w, w);
    }
    if (tid < 32) s_bd[tid] = dup2(cob[tid]);

    // input tile with 3px halo (zero pad)
    for (int i = tid; i < 2 * (THB + 6) * 72; i += 256) {
        int plane = i / ((THB + 6) * 72);
        int rem   = i - plane * ((THB + 6) * 72);
        int r  = rem / 72;
        int cc = rem - r * 72;
        int h = tyb - 3 + r;
        int w = txb - 3 + cc;
        float v = 0.f;
        if (cc < 70 && h >= 0 && h < H_ && w >= 0 && w < W_)
            v = (plane ? g_ca : g_cm)[((unsigned)b * H_ + h) * W_ + w];
        s_in[plane][r][cc] = v;
    }
    __syncthreads();

    const int cg  = tid >> 5;       // channel group: channels cg*4 .. cg*4+3 (uniform per warp)
    const int oct = tid & 31;
    const int ox  = oct & 7;        // pixel octet within row: cols ox*8 .. ox*8+7
    const int oy  = oct >> 3;       // row within tile

    u64 acc[4][4];  // [pair][local channel]
#pragma unroll
    for (int i = 0; i < 4; i++)
#pragma unroll
        for (int c = 0; c < 4; c++) acc[i][c] = s_bd[cg * 4 + c];

#pragma unroll 1
    for (int j = 0; j < 2; j++) {
#pragma unroll 1
        for (int dy = 0; dy < 7; dy++) {
            // cache 16-float window (32B-aligned: ox*8 floats)
            const float4* __restrict__ rp = (const float4*)&s_in[j][oy + dy][ox * 8];
            float4 q0 = rp[0], q1 = rp[1], q2 = rp[2], q3 = rp[3];
            float win[16] = {q0.x,q0.y,q0.z,q0.w, q1.x,q1.y,q1.z,q1.w,
                             q2.x,q2.y,q2.z,q2.w, q3.x,q3.y,q3.z,q3.w};
            const int tapbase = j * 49 + dy * 7;
#pragma unroll
            for (int dx = 0; dx < 7; dx++) {
                const ulonglong2* __restrict__ wp2 = (const ulonglong2*)&s_wd[tapbase + dx][cg * 4];
                ulonglong2 wa = wp2[0];
                ulonglong2 wb = wp2[1];
#pragma unroll
                for (int i = 0; i < 4; i++) {
                    u64 vv = pack2(win[dx + 2*i], win[dx + 2*i + 1]);
                    acc[i][0] = fma2(vv, wa.x, acc[i][0]);
                    acc[i][1] = fma2(vv, wa.y, acc[i][1]);
                    acc[i][2] = fma2(vv, wb.x, acc[i][2]);
                    acc[i][3] = fma2(vv, wb.y, acc[i][3]);
                }
            }
        }
    }

    // epilogue: sigmoid(att) * fs
    const int h  = tyb + oy;
    const int w0 = txb + ox * 8;
#pragma unroll
    for (int c = 0; c < 4; c++) {
        unsigned base = (((unsigned)(b * 32 + cg * 4 + c)) * 512u + h) * 512u + w0;
#pragma unroll
        for (int i = 0; i < 4; i++) {
            float a0, a1; unpack2(acc[i][c], a0, a1);
            float2 f = *(const float2*)&g_fs[base + 2*i];
            *(float2*)&out[base + 2*i] = make_float2(fsigmoid(a0) * f.x,
                                                     fsigmoid(a1) * f.y);
        }
    }
}

extern "C" void kernel_launch(void* const* d_in, const int* in_sizes, int n_in,
                              void* d_out, int out_size)
{
    (void)in_sizes; (void)n_in; (void)out_size;
    const float* x      = (const float*)d_in[0];
    const float* mlp_w  = (const float*)d_in[1];
    const float* mlp_b  = (const float*)d_in[2];
    const float* conv_w = (const float*)d_in[3];
    const float* conv_b = (const float*)d_in[4];
    const float* cow    = (const float*)d_in[5];
    const float* cob    = (const float*)d_in[6];
    float* out = (float*)d_out;

    kernelA<<<dim3(2, 256, 8), 256>>>(x, mlp_w, mlp_b, conv_w, conv_b);
    kernelB<<<dim3(8, 128, 8), 256>>>(cow, cob, out);
}